// round 2
// baseline (speedup 1.0000x reference)
#include <cuda_runtime.h>
#include <cuda_bf16.h>

// FALayer: z[dst] += h[src] * e   where
//   e = (tanh(p_dst[dst] + p_src[src] + b) + tanh(yn*yw + (1-yn)*nw)) * 0.5 * d[dst] * d[src]
//   p_dst = h @ W[:, :D], p_src = h @ W[:, D:]
//
// Inputs (metadata order):
//  0: h      [N, D] f32      (N=100000, D=128)
//  1: d      [N]    f32
//  2: yes_no [E]    f32      (E=1600000)
//  3: gate_w [1, 2D] f32
//  4: gate_b [1]    f32
//  5: yes_weight [] f32
//  6: no_weight  [] f32
//  7: src    [E]    i32   (JAX x64 disabled -> int64 request silently becomes int32)
//  8: dst    [E]    i32
// Output: z [N, D] f32

#define D 128
#define MAX_N 100352

__device__ float g_pdst[MAX_N];
__device__ float g_psrc[MAX_N];

// One warp per node: dot(h[n], w_dst) and dot(h[n], w_src) via float4 + shfl.
__global__ void proj_kernel(const float* __restrict__ h,
                            const float* __restrict__ gate_w,
                            int n_nodes) {
    int warp = (blockIdx.x * blockDim.x + threadIdx.x) >> 5;
    int lane = threadIdx.x & 31;
    if (warp >= n_nodes) return;

    const float4* hrow = reinterpret_cast<const float4*>(h + (size_t)warp * D);
    const float4* wd = reinterpret_cast<const float4*>(gate_w);
    const float4* ws = reinterpret_cast<const float4*>(gate_w + D);

    float4 hv = hrow[lane];
    float4 wdv = wd[lane];
    float4 wsv = ws[lane];

    float pd = hv.x * wdv.x + hv.y * wdv.y + hv.z * wdv.z + hv.w * wdv.w;
    float ps = hv.x * wsv.x + hv.y * wsv.y + hv.z * wsv.z + hv.w * wsv.w;

    #pragma unroll
    for (int off = 16; off > 0; off >>= 1) {
        pd += __shfl_xor_sync(0xFFFFFFFF, pd, off);
        ps += __shfl_xor_sync(0xFFFFFFFF, ps, off);
    }
    if (lane == 0) {
        g_pdst[warp] = pd;
        g_psrc[warp] = ps;
    }
}

// One warp per edge: compute scalar coefficient, gather h[src] row (float4 per
// lane), scatter-add into z[dst] with 4 atomicAdds per lane (compiles to REDG).
__global__ void edge_kernel(const float* __restrict__ h,
                            const float* __restrict__ dnorm,
                            const float* __restrict__ yes_no,
                            const float* __restrict__ gate_b,
                            const float* __restrict__ yes_w,
                            const float* __restrict__ no_w,
                            const int* __restrict__ src,
                            const int* __restrict__ dst,
                            float* __restrict__ z,
                            int n_edges) {
    int e = (blockIdx.x * blockDim.x + threadIdx.x) >> 5;
    int lane = threadIdx.x & 31;
    if (e >= n_edges) return;

    int s = src[e];
    int t = dst[e];

    float yn = yes_no[e];
    float g = tanhf(g_pdst[t] + g_psrc[s] + gate_b[0]);
    float y = tanhf(yn * yes_w[0] + (1.0f - yn) * no_w[0]);
    float coef = (g + y) * 0.5f * dnorm[t] * dnorm[s];

    const float4* hrow = reinterpret_cast<const float4*>(h + (size_t)s * D);
    float4 v = hrow[lane];

    float* zrow = z + (size_t)t * D + lane * 4;
    atomicAdd(zrow + 0, v.x * coef);
    atomicAdd(zrow + 1, v.y * coef);
    atomicAdd(zrow + 2, v.z * coef);
    atomicAdd(zrow + 3, v.w * coef);
}

extern "C" void kernel_launch(void* const* d_in, const int* in_sizes, int n_in,
                              void* d_out, int out_size) {
    const float* h       = (const float*)d_in[0];
    const float* dnorm   = (const float*)d_in[1];
    const float* yes_no  = (const float*)d_in[2];
    const float* gate_b  = (const float*)d_in[4];
    const float* yes_w   = (const float*)d_in[5];
    const float* no_w    = (const float*)d_in[6];
    const float* gate_w  = (const float*)d_in[3];
    const int* src       = (const int*)d_in[7];
    const int* dst       = (const int*)d_in[8];
    float* z = (float*)d_out;

    int n_nodes = in_sizes[1];
    int n_edges = in_sizes[2];

    // Zero the output accumulator.
    cudaMemsetAsync(z, 0, (size_t)out_size * sizeof(float), 0);

    // Per-node projections: one warp per node.
    {
        int threads = 256;
        int warps_per_block = threads / 32;
        int blocks = (n_nodes + warps_per_block - 1) / warps_per_block;
        proj_kernel<<<blocks, threads>>>(h, gate_w, n_nodes);
    }

    // Per-edge scatter: one warp per edge.
    {
        int threads = 256;
        int warps_per_block = threads / 32;
        int blocks = (n_edges + warps_per_block - 1) / warps_per_block;
        edge_kernel<<<blocks, threads>>>(h, dnorm, yes_no, gate_b, yes_w, no_w,
                                         src, dst, z, n_edges);
    }
}

// round 3
// speedup vs baseline: 1.5924x; 1.5924x over previous
#include <cuda_runtime.h>
#include <cuda_bf16.h>

// FALayer via dst-bucketed two-phase scatter:
//   1) proj: p_dst/p_src per node
//   2) count: histogram of dst
//   3) scan: exclusive prefix -> bucket offsets (+ mutable cursors)
//   4) scatter: per edge compute coef, write {src, coef} into dst's bucket
//   5) gather: one warp per node, accumulate bucket in registers, store z row once
//
// Inputs (metadata order):
//  0: h [N,128] f32   1: d [N] f32   2: yes_no [E] f32   3: gate_w [1,256] f32
//  4: gate_b [1] f32  5: yes_weight [] f32  6: no_weight [] f32
//  7: src [E] i32     8: dst [E] i32      (JAX x64 off -> int32)
// Output: z [N,128] f32

#define D 128
#define MAX_N 100352
#define MAX_E 1605632
#define SCAN_T 1024

__device__ float g_pdst[MAX_N];
__device__ float g_psrc[MAX_N];
__device__ int g_deg[MAX_N];
__device__ int g_offs[MAX_N + 1];
__device__ int g_cursor[MAX_N];
__device__ long long g_pairs[MAX_E];   // low 32: src idx, high 32: coef bits

// ---------------------------------------------------------------- proj + zero
__global__ void proj_kernel(const float* __restrict__ h,
                            const float* __restrict__ gate_w,
                            int n_nodes) {
    int warp = (blockIdx.x * blockDim.x + threadIdx.x) >> 5;
    int lane = threadIdx.x & 31;
    if (warp >= n_nodes) return;

    const float4* hrow = reinterpret_cast<const float4*>(h + (size_t)warp * D);
    const float4* wd = reinterpret_cast<const float4*>(gate_w);
    const float4* ws = reinterpret_cast<const float4*>(gate_w + D);

    float4 hv = hrow[lane];
    float4 wdv = wd[lane];
    float4 wsv = ws[lane];

    float pd = hv.x * wdv.x + hv.y * wdv.y + hv.z * wdv.z + hv.w * wdv.w;
    float ps = hv.x * wsv.x + hv.y * wsv.y + hv.z * wsv.z + hv.w * wsv.w;

    #pragma unroll
    for (int off = 16; off > 0; off >>= 1) {
        pd += __shfl_xor_sync(0xFFFFFFFF, pd, off);
        ps += __shfl_xor_sync(0xFFFFFFFF, ps, off);
    }
    if (lane == 0) {
        g_pdst[warp] = pd;
        g_psrc[warp] = ps;
        g_deg[warp] = 0;   // zero histogram alongside
    }
}

// ---------------------------------------------------------------- histogram
__global__ void count_kernel(const int* __restrict__ dst, int n_edges) {
    int e = blockIdx.x * blockDim.x + threadIdx.x;
    if (e >= n_edges) return;
    atomicAdd(&g_deg[dst[e]], 1);
}

// ---------------------------------------------------------------- scan (1 block)
__global__ void scan_kernel(int n_nodes, int n_edges) {
    __shared__ int sums[SCAN_T];
    int t = threadIdx.x;
    int chunk = (n_nodes + SCAN_T - 1) / SCAN_T;
    int begin = t * chunk;
    int endi = min(begin + chunk, n_nodes);

    int s = 0;
    for (int i = begin; i < endi; i++) s += g_deg[i];
    sums[t] = s;
    __syncthreads();

    // Hillis-Steele inclusive scan over SCAN_T partials
    #pragma unroll
    for (int off = 1; off < SCAN_T; off <<= 1) {
        int v = (t >= off) ? sums[t - off] : 0;
        __syncthreads();
        sums[t] += v;
        __syncthreads();
    }

    int run = (t == 0) ? 0 : sums[t - 1];
    for (int i = begin; i < endi; i++) {
        g_offs[i] = run;
        g_cursor[i] = run;
        run += g_deg[i];
    }
    if (t == 0) g_offs[n_nodes] = n_edges;
}

// ---------------------------------------------------------------- scatter
__global__ void scatter_kernel(const float* __restrict__ dnorm,
                               const float* __restrict__ yes_no,
                               const float* __restrict__ gate_b,
                               const float* __restrict__ yes_w,
                               const float* __restrict__ no_w,
                               const int* __restrict__ src,
                               const int* __restrict__ dst,
                               int n_edges) {
    int e = blockIdx.x * blockDim.x + threadIdx.x;
    if (e >= n_edges) return;

    int s = src[e];
    int t = dst[e];

    float yn = yes_no[e];
    float g = tanhf(g_pdst[t] + g_psrc[s] + gate_b[0]);
    float y = tanhf(yn * yes_w[0] + (1.0f - yn) * no_w[0]);
    float coef = (g + y) * 0.5f * dnorm[t] * dnorm[s];

    int pos = atomicAdd(&g_cursor[t], 1);
    long long packed = ((long long)__float_as_int(coef) << 32) | (unsigned int)s;
    g_pairs[pos] = packed;
}

// ---------------------------------------------------------------- gather
// One warp per dst node: register accumulation over its bucket, single store.
__global__ void gather_kernel(const float* __restrict__ h,
                              float* __restrict__ z,
                              int n_nodes) {
    int node = (blockIdx.x * blockDim.x + threadIdx.x) >> 5;
    int lane = threadIdx.x & 31;
    if (node >= n_nodes) return;

    int start = g_offs[node];
    int end = g_offs[node + 1];

    float4 acc = make_float4(0.f, 0.f, 0.f, 0.f);

    int i = start;
    // unroll by 2 for memory-level parallelism
    for (; i + 1 < end; i += 2) {
        long long p0 = g_pairs[i];
        long long p1 = g_pairs[i + 1];
        int s0 = (int)(unsigned int)(p0 & 0xffffffffLL);
        int s1 = (int)(unsigned int)(p1 & 0xffffffffLL);
        float c0 = __int_as_float((int)(p0 >> 32));
        float c1 = __int_as_float((int)(p1 >> 32));
        float4 v0 = reinterpret_cast<const float4*>(h + (size_t)s0 * D)[lane];
        float4 v1 = reinterpret_cast<const float4*>(h + (size_t)s1 * D)[lane];
        acc.x += v0.x * c0 + v1.x * c1;
        acc.y += v0.y * c0 + v1.y * c1;
        acc.z += v0.z * c0 + v1.z * c1;
        acc.w += v0.w * c0 + v1.w * c1;
    }
    if (i < end) {
        long long p0 = g_pairs[i];
        int s0 = (int)(unsigned int)(p0 & 0xffffffffLL);
        float c0 = __int_as_float((int)(p0 >> 32));
        float4 v0 = reinterpret_cast<const float4*>(h + (size_t)s0 * D)[lane];
        acc.x += v0.x * c0;
        acc.y += v0.y * c0;
        acc.z += v0.z * c0;
        acc.w += v0.w * c0;
    }

    reinterpret_cast<float4*>(z + (size_t)node * D)[lane] = acc;
}

extern "C" void kernel_launch(void* const* d_in, const int* in_sizes, int n_in,
                              void* d_out, int out_size) {
    const float* h       = (const float*)d_in[0];
    const float* dnorm   = (const float*)d_in[1];
    const float* yes_no  = (const float*)d_in[2];
    const float* gate_w  = (const float*)d_in[3];
    const float* gate_b  = (const float*)d_in[4];
    const float* yes_w   = (const float*)d_in[5];
    const float* no_w    = (const float*)d_in[6];
    const int* src       = (const int*)d_in[7];
    const int* dst       = (const int*)d_in[8];
    float* z = (float*)d_out;

    int n_nodes = in_sizes[1];
    int n_edges = in_sizes[2];

    // 1) projections + histogram zeroing (one warp per node)
    {
        int threads = 256;
        int blocks = (n_nodes + 7) / 8;
        proj_kernel<<<blocks, threads>>>(h, gate_w, n_nodes);
    }
    // 2) dst histogram
    {
        int threads = 256;
        int blocks = (n_edges + threads - 1) / threads;
        count_kernel<<<blocks, threads>>>(dst, n_edges);
    }
    // 3) prefix scan -> offsets + cursors
    scan_kernel<<<1, SCAN_T>>>(n_nodes, n_edges);
    // 4) scatter edges into dst buckets with precomputed coefficients
    {
        int threads = 256;
        int blocks = (n_edges + threads - 1) / threads;
        scatter_kernel<<<blocks, threads>>>(dnorm, yes_no, gate_b, yes_w, no_w,
                                            src, dst, n_edges);
    }
    // 5) per-node register accumulation, single z-row store (no atomics)
    {
        int threads = 256;
        int blocks = (n_nodes + 7) / 8;
        gather_kernel<<<blocks, threads>>>(h, z, n_nodes);
    }
}

// round 4
// speedup vs baseline: 1.8035x; 1.1326x over previous
#include <cuda_runtime.h>
#include <cuda_fp16.h>

// FALayer via dst-bucketed two-phase scatter + fp16 h-copy for the gather:
//   1) proj: p_dst/p_src per node, pack (p,d) float2, convert h row -> fp16
//   2) count: histogram of dst
//   3) scan: exclusive prefix -> bucket offsets (+ cursors)
//   4) scatter: per edge compute coef, write {src, coef} into dst bucket
//   5) gather: one warp per node, f32 register accumulation over fp16 rows
//
// Inputs: 0 h[N,128]f32  1 d[N]f32  2 yes_no[E]f32  3 gate_w[1,256]f32
//         4 gate_b[1]f32 5 yes_w f32 6 no_w f32  7 src[E]i32  8 dst[E]i32
// Output: z[N,128]f32

#define D 128
#define MAX_N 100352
#define MAX_E 1605632
#define SCAN_T 1024

__device__ float2 g_pd2[MAX_N];            // (p_dst, d) per node
__device__ float2 g_ps2[MAX_N];            // (p_src, d) per node
__device__ int g_deg[MAX_N];
__device__ int g_offs[MAX_N + 1];
__device__ int g_cursor[MAX_N];
__device__ long long g_pairs[MAX_E];       // low 32: src idx, high 32: coef bits
__device__ __half2 g_h2[(size_t)MAX_N * (D / 2)];  // fp16 copy of h (25.7 MB)

// ------------------------------------------------ proj + fp16 convert + zero
__global__ void proj_kernel(const float* __restrict__ h,
                            const float* __restrict__ dnorm,
                            const float* __restrict__ gate_w,
                            int n_nodes) {
    int warp = (blockIdx.x * blockDim.x + threadIdx.x) >> 5;
    int lane = threadIdx.x & 31;
    if (warp >= n_nodes) return;

    const float4* hrow = reinterpret_cast<const float4*>(h + (size_t)warp * D);
    const float4* wd = reinterpret_cast<const float4*>(gate_w);
    const float4* ws = reinterpret_cast<const float4*>(gate_w + D);

    float4 hv = hrow[lane];
    float4 wdv = wd[lane];
    float4 wsv = ws[lane];

    // fp16 copy: 4 floats -> 2 half2, contiguous per lane
    __half2 a = __floats2half2_rn(hv.x, hv.y);
    __half2 b = __floats2half2_rn(hv.z, hv.w);
    size_t base = (size_t)warp * (D / 2) + lane * 2;
    g_h2[base] = a;
    g_h2[base + 1] = b;

    float pd = hv.x * wdv.x + hv.y * wdv.y + hv.z * wdv.z + hv.w * wdv.w;
    float ps = hv.x * wsv.x + hv.y * wsv.y + hv.z * wsv.z + hv.w * wsv.w;

    #pragma unroll
    for (int off = 16; off > 0; off >>= 1) {
        pd += __shfl_xor_sync(0xFFFFFFFF, pd, off);
        ps += __shfl_xor_sync(0xFFFFFFFF, ps, off);
    }
    if (lane == 0) {
        float dn = dnorm[warp];
        g_pd2[warp] = make_float2(pd, dn);
        g_ps2[warp] = make_float2(ps, dn);
        g_deg[warp] = 0;
    }
}

// ---------------------------------------------------------------- histogram
__global__ void count_kernel(const int* __restrict__ dst, int n_edges) {
    int e = blockIdx.x * blockDim.x + threadIdx.x;
    if (e >= n_edges) return;
    atomicAdd(&g_deg[dst[e]], 1);
}

// ---------------------------------------------------------------- scan (1 block)
__global__ void scan_kernel(int n_nodes, int n_edges) {
    __shared__ int sums[SCAN_T];
    int t = threadIdx.x;
    int chunk = (n_nodes + SCAN_T - 1) / SCAN_T;
    int begin = t * chunk;
    int endi = min(begin + chunk, n_nodes);

    int s = 0;
    for (int i = begin; i < endi; i++) s += g_deg[i];
    sums[t] = s;
    __syncthreads();

    #pragma unroll
    for (int off = 1; off < SCAN_T; off <<= 1) {
        int v = (t >= off) ? sums[t - off] : 0;
        __syncthreads();
        sums[t] += v;
        __syncthreads();
    }

    int run = (t == 0) ? 0 : sums[t - 1];
    for (int i = begin; i < endi; i++) {
        g_offs[i] = run;
        g_cursor[i] = run;
        run += g_deg[i];
    }
    if (t == 0) g_offs[n_nodes] = n_edges;
}

// ---------------------------------------------------------------- scatter
__global__ void scatter_kernel(const float* __restrict__ yes_no,
                               const float* __restrict__ gate_b,
                               const float* __restrict__ yes_w,
                               const float* __restrict__ no_w,
                               const int* __restrict__ src,
                               const int* __restrict__ dst,
                               int n_edges) {
    int e = blockIdx.x * blockDim.x + threadIdx.x;
    if (e >= n_edges) return;

    int s = src[e];
    int t = dst[e];

    float2 pdt = g_pd2[t];   // (p_dst[t], d[t])  one 8B random read
    float2 pss = g_ps2[s];   // (p_src[s], d[s])  one 8B random read

    float yn = yes_no[e];
    float g = tanhf(pdt.x + pss.x + gate_b[0]);
    float y = tanhf(yn * yes_w[0] + (1.0f - yn) * no_w[0]);
    float coef = (g + y) * 0.5f * pdt.y * pss.y;

    int pos = atomicAdd(&g_cursor[t], 1);
    long long packed = ((long long)__float_as_int(coef) << 32) | (unsigned int)s;
    g_pairs[pos] = packed;
}

// ---------------------------------------------------------------- gather
// One warp per dst node: f32 register accumulation over fp16 rows, 1 store.
__device__ __forceinline__ void fma_row(float4& acc, long long p, int lane) {
    int s = (int)(unsigned int)(p & 0xffffffffLL);
    float c = __int_as_float((int)(p >> 32));
    // 8B load: 2 half2 = 4 halves for this lane
    const uint2* row = reinterpret_cast<const uint2*>(&g_h2[(size_t)s * (D / 2)]);
    uint2 raw = row[lane];
    __half2 a = *reinterpret_cast<__half2*>(&raw.x);
    __half2 b = *reinterpret_cast<__half2*>(&raw.y);
    float2 fa = __half22float2(a);
    float2 fb = __half22float2(b);
    acc.x += fa.x * c;
    acc.y += fa.y * c;
    acc.z += fb.x * c;
    acc.w += fb.y * c;
}

__global__ void gather_kernel(float* __restrict__ z, int n_nodes) {
    int node = (blockIdx.x * blockDim.x + threadIdx.x) >> 5;
    int lane = threadIdx.x & 31;
    if (node >= n_nodes) return;

    int start = g_offs[node];
    int end = g_offs[node + 1];

    float4 acc = make_float4(0.f, 0.f, 0.f, 0.f);

    int i = start;
    for (; i + 3 < end; i += 4) {
        long long p0 = g_pairs[i];
        long long p1 = g_pairs[i + 1];
        long long p2 = g_pairs[i + 2];
        long long p3 = g_pairs[i + 3];
        fma_row(acc, p0, lane);
        fma_row(acc, p1, lane);
        fma_row(acc, p2, lane);
        fma_row(acc, p3, lane);
    }
    for (; i < end; i++) {
        fma_row(acc, g_pairs[i], lane);
    }

    reinterpret_cast<float4*>(z + (size_t)node * D)[lane] = acc;
}

extern "C" void kernel_launch(void* const* d_in, const int* in_sizes, int n_in,
                              void* d_out, int out_size) {
    const float* h       = (const float*)d_in[0];
    const float* dnorm   = (const float*)d_in[1];
    const float* yes_no  = (const float*)d_in[2];
    const float* gate_w  = (const float*)d_in[3];
    const float* gate_b  = (const float*)d_in[4];
    const float* yes_w   = (const float*)d_in[5];
    const float* no_w    = (const float*)d_in[6];
    const int* src       = (const int*)d_in[7];
    const int* dst       = (const int*)d_in[8];
    float* z = (float*)d_out;

    int n_nodes = in_sizes[1];
    int n_edges = in_sizes[2];

    {   // proj + fp16 convert + histogram zero
        int blocks = (n_nodes + 7) / 8;
        proj_kernel<<<blocks, 256>>>(h, dnorm, gate_w, n_nodes);
    }
    {   // dst histogram
        int blocks = (n_edges + 255) / 256;
        count_kernel<<<blocks, 256>>>(dst, n_edges);
    }
    scan_kernel<<<1, SCAN_T>>>(n_nodes, n_edges);
    {   // scatter with packed scalar reads
        int blocks = (n_edges + 255) / 256;
        scatter_kernel<<<blocks, 256>>>(yes_no, gate_b, yes_w, no_w,
                                        src, dst, n_edges);
    }
    {   // per-node accumulation, single z-row store
        int blocks = (n_nodes + 7) / 8;
        gather_kernel<<<blocks, 256>>>(z, n_nodes);
    }
}

// round 5
// speedup vs baseline: 4.4509x; 2.4680x over previous
#include <cuda_runtime.h>
#include <cuda_fp16.h>

// FALayer, dst-bucketed:
//   proj (+fp16 h copy) -> count -> 3-phase coalesced scan -> scatter -> gather
// Inputs: 0 h[N,128]f32  1 d[N]f32  2 yes_no[E]f32  3 gate_w[1,256]f32
//         4 gate_b[1]f32 5 yes_w f32 6 no_w f32  7 src[E]i32  8 dst[E]i32
// Output: z[N,128]f32

#define D 128
#define MAX_N 100352
#define MAX_E 1605632
#define SCAN_B 512                      // nodes per scan block (== threads)
#define MAX_SCAN_BLOCKS 256

__device__ float2 g_pd2[MAX_N];
__device__ float2 g_ps2[MAX_N];
__device__ int g_deg[MAX_N];
__device__ int g_offs[MAX_N + 1];
__device__ int g_cursor[MAX_N];
__device__ int g_bsum[MAX_SCAN_BLOCKS];
__device__ int g_boff[MAX_SCAN_BLOCKS];
__device__ long long g_pairs[MAX_E];                 // lo32 src, hi32 coef bits
__device__ __half2 g_h2[(size_t)MAX_N * (D / 2)];    // fp16 h copy (25.7 MB)

// ------------------------------------------------ proj + fp16 convert + zero
__global__ void proj_kernel(const float* __restrict__ h,
                            const float* __restrict__ dnorm,
                            const float* __restrict__ gate_w,
                            int n_nodes) {
    int warp = (blockIdx.x * blockDim.x + threadIdx.x) >> 5;
    int lane = threadIdx.x & 31;
    if (warp >= n_nodes) return;

    const float4* hrow = reinterpret_cast<const float4*>(h + (size_t)warp * D);
    const float4* wd = reinterpret_cast<const float4*>(gate_w);
    const float4* ws = reinterpret_cast<const float4*>(gate_w + D);

    float4 hv = hrow[lane];
    float4 wdv = wd[lane];
    float4 wsv = ws[lane];

    __half2 a = __floats2half2_rn(hv.x, hv.y);
    __half2 b = __floats2half2_rn(hv.z, hv.w);
    size_t base = (size_t)warp * (D / 2) + lane * 2;
    g_h2[base] = a;
    g_h2[base + 1] = b;

    float pd = hv.x * wdv.x + hv.y * wdv.y + hv.z * wdv.z + hv.w * wdv.w;
    float ps = hv.x * wsv.x + hv.y * wsv.y + hv.z * wsv.z + hv.w * wsv.w;

    #pragma unroll
    for (int off = 16; off > 0; off >>= 1) {
        pd += __shfl_xor_sync(0xFFFFFFFF, pd, off);
        ps += __shfl_xor_sync(0xFFFFFFFF, ps, off);
    }
    if (lane == 0) {
        float dn = dnorm[warp];
        g_pd2[warp] = make_float2(pd, dn);
        g_ps2[warp] = make_float2(ps, dn);
        g_deg[warp] = 0;
    }
}

// ---------------------------------------------------------------- histogram
__global__ void count_kernel(const int* __restrict__ dst, int n_edges) {
    int e = blockIdx.x * blockDim.x + threadIdx.x;
    if (e >= n_edges) return;
    atomicAdd(&g_deg[dst[e]], 1);
}

// ----------------------------------------------------- scan phase A: block sums
__global__ void scanA_kernel(int n_nodes) {
    __shared__ int red[SCAN_B];
    int t = threadIdx.x;
    int i = blockIdx.x * SCAN_B + t;
    red[t] = (i < n_nodes) ? g_deg[i] : 0;
    __syncthreads();
    #pragma unroll
    for (int off = SCAN_B / 2; off > 0; off >>= 1) {
        if (t < off) red[t] += red[t + off];
        __syncthreads();
    }
    if (t == 0) g_bsum[blockIdx.x] = red[0];
}

// --------------------------------------------- scan phase B: scan block sums
__global__ void scanB_kernel(int n_blocks, int n_nodes, int n_edges) {
    __shared__ int s[MAX_SCAN_BLOCKS];
    int t = threadIdx.x;
    s[t] = (t < n_blocks) ? g_bsum[t] : 0;
    __syncthreads();
    #pragma unroll
    for (int off = 1; off < MAX_SCAN_BLOCKS; off <<= 1) {
        int v = (t >= off) ? s[t - off] : 0;
        __syncthreads();
        s[t] += v;
        __syncthreads();
    }
    if (t < n_blocks) g_boff[t] = (t == 0) ? 0 : s[t - 1];  // exclusive
    if (t == 0) g_offs[n_nodes] = n_edges;
}

// --------------------------------------- scan phase C: block-local exclusive
__global__ void scanC_kernel(int n_nodes) {
    __shared__ int s[SCAN_B];
    int t = threadIdx.x;
    int i = blockIdx.x * SCAN_B + t;
    int v = (i < n_nodes) ? g_deg[i] : 0;
    s[t] = v;
    __syncthreads();
    #pragma unroll
    for (int off = 1; off < SCAN_B; off <<= 1) {
        int u = (t >= off) ? s[t - off] : 0;
        __syncthreads();
        s[t] += u;
        __syncthreads();
    }
    if (i < n_nodes) {
        int excl = s[t] - v + g_boff[blockIdx.x];
        g_offs[i] = excl;
        g_cursor[i] = excl;
    }
}

// ---------------------------------------------------------------- scatter
__global__ void scatter_kernel(const float* __restrict__ yes_no,
                               const float* __restrict__ gate_b,
                               const float* __restrict__ yes_w,
                               const float* __restrict__ no_w,
                               const int* __restrict__ src,
                               const int* __restrict__ dst,
                               int n_edges) {
    int e = blockIdx.x * blockDim.x + threadIdx.x;
    if (e >= n_edges) return;

    int s = src[e];
    int t = dst[e];

    float2 pdt = g_pd2[t];
    float2 pss = g_ps2[s];

    float yn = yes_no[e];
    float g = tanhf(pdt.x + pss.x + gate_b[0]);
    float y = tanhf(yn * yes_w[0] + (1.0f - yn) * no_w[0]);
    float coef = (g + y) * 0.5f * pdt.y * pss.y;

    int pos = atomicAdd(&g_cursor[t], 1);
    long long packed = ((long long)__float_as_int(coef) << 32) | (unsigned int)s;
    g_pairs[pos] = packed;
}

// ---------------------------------------------------------------- gather
// 16 lanes per node (2 nodes per warp). Each lane owns one uint4 (16B = 8
// halves) of the 256B fp16 row; unroll 4 -> up to 8 outstanding row loads/warp.
__device__ __forceinline__ void fma_row16(float acc[8], long long p, int sub) {
    int s = (int)(unsigned int)(p & 0xffffffffLL);
    float c = __int_as_float((int)(p >> 32));
    const uint4* row = reinterpret_cast<const uint4*>(g_h2) + (size_t)s * 16;
    uint4 raw = row[sub];
    float2 f0 = __half22float2(*reinterpret_cast<__half2*>(&raw.x));
    float2 f1 = __half22float2(*reinterpret_cast<__half2*>(&raw.y));
    float2 f2 = __half22float2(*reinterpret_cast<__half2*>(&raw.z));
    float2 f3 = __half22float2(*reinterpret_cast<__half2*>(&raw.w));
    acc[0] += f0.x * c; acc[1] += f0.y * c;
    acc[2] += f1.x * c; acc[3] += f1.y * c;
    acc[4] += f2.x * c; acc[5] += f2.y * c;
    acc[6] += f3.x * c; acc[7] += f3.y * c;
}

__global__ void gather_kernel(float* __restrict__ z, int n_nodes) {
    int gwarp = (blockIdx.x * blockDim.x + threadIdx.x) >> 5;
    int lane = threadIdx.x & 31;
    int half = lane >> 4;       // which node within the warp
    int sub = lane & 15;        // lane within the 16-lane group
    int node = gwarp * 2 + half;
    if (node >= n_nodes) return;

    int start = g_offs[node];
    int end = g_offs[node + 1];

    float acc[8] = {0.f, 0.f, 0.f, 0.f, 0.f, 0.f, 0.f, 0.f};

    int i = start;
    for (; i + 3 < end; i += 4) {
        long long p0 = g_pairs[i];
        long long p1 = g_pairs[i + 1];
        long long p2 = g_pairs[i + 2];
        long long p3 = g_pairs[i + 3];
        fma_row16(acc, p0, sub);
        fma_row16(acc, p1, sub);
        fma_row16(acc, p2, sub);
        fma_row16(acc, p3, sub);
    }
    for (; i < end; i++) {
        fma_row16(acc, g_pairs[i], sub);
    }

    // z row: 512B over 16 lanes -> 2 float4 stores per lane
    float4* zrow = reinterpret_cast<float4*>(z + (size_t)node * D);
    zrow[sub * 2]     = make_float4(acc[0], acc[1], acc[2], acc[3]);
    zrow[sub * 2 + 1] = make_float4(acc[4], acc[5], acc[6], acc[7]);
}

extern "C" void kernel_launch(void* const* d_in, const int* in_sizes, int n_in,
                              void* d_out, int out_size) {
    const float* h       = (const float*)d_in[0];
    const float* dnorm   = (const float*)d_in[1];
    const float* yes_no  = (const float*)d_in[2];
    const float* gate_w  = (const float*)d_in[3];
    const float* gate_b  = (const float*)d_in[4];
    const float* yes_w   = (const float*)d_in[5];
    const float* no_w    = (const float*)d_in[6];
    const int* src       = (const int*)d_in[7];
    const int* dst       = (const int*)d_in[8];
    float* z = (float*)d_out;

    int n_nodes = in_sizes[1];
    int n_edges = in_sizes[2];
    int scan_blocks = (n_nodes + SCAN_B - 1) / SCAN_B;   // 196 for N=100000

    {   // proj + fp16 convert + histogram zero
        int blocks = (n_nodes + 7) / 8;
        proj_kernel<<<blocks, 256>>>(h, dnorm, gate_w, n_nodes);
    }
    {   // dst histogram
        int blocks = (n_edges + 255) / 256;
        count_kernel<<<blocks, 256>>>(dst, n_edges);
    }
    // coalesced 3-phase exclusive scan
    scanA_kernel<<<scan_blocks, SCAN_B>>>(n_nodes);
    scanB_kernel<<<1, MAX_SCAN_BLOCKS>>>(scan_blocks, n_nodes, n_edges);
    scanC_kernel<<<scan_blocks, SCAN_B>>>(n_nodes);
    {   // scatter with packed scalar reads
        int blocks = (n_edges + 255) / 256;
        scatter_kernel<<<blocks, 256>>>(yes_no, gate_b, yes_w, no_w,
                                        src, dst, n_edges);
    }
    {   // gather: 2 nodes per warp, 16 lanes per node
        int warps_needed = (n_nodes + 1) / 2;
        int blocks = (warps_needed + 7) / 8;
        gather_kernel<<<blocks, 256>>>(z, n_nodes);
    }
}